// round 2
// baseline (speedup 1.0000x reference)
#include <cuda_runtime.h>
#include <math.h>

#define DIM   768
#define MAXN  10000
#define MAXE  100000

// ---------------- scratch (static device globals; no allocation) ----------------
__device__ float g_h [MAXN * DIM];   // h = x @ W (per-layer, reused)
__device__ float g_x1[MAXN * DIM];   // layer-1 output (relu'd) = layer-2 input
__device__ float g_as[MAXN];
__device__ float g_ad[MAXN];
__device__ float g_m [MAXN];
__device__ float g_den[MAXN];
__device__ float g_e [MAXE + MAXN];  // per-edge logits, then exp values

// ---------------- helpers ----------------
__device__ __forceinline__ void atomicMaxF(float* addr, float value) {
    int* ai = (int*)addr;
    int old = *ai;
    while (__int_as_float(old) < value) {
        int assumed = old;
        old = atomicCAS(ai, assumed, __float_as_int(value));
        if (old == assumed) break;
    }
}

// ---------------- SGEMM: C[MxN] = A[MxK] @ B[KxN], row-major ----------------
// BM=128, BN=128, BK=8, 8x8 per thread, 256 threads.
__global__ void sgemm128(int M, int N, int K,
                         const float* __restrict__ A,
                         const float* __restrict__ B,
                         float* __restrict__ C) {
    const int BM = 128, BN = 128, BK = 8, TM = 8, TN = 8;
    __shared__ float As[BK][BM];
    __shared__ float Bs[BK][BN];

    const int bcol = blockIdx.x;      // N tile
    const int brow = blockIdx.y;      // M tile
    const int tid  = threadIdx.x;     // 0..255

    const int trow = tid / (BN / TN); // 0..15
    const int tcol = tid % (BN / TN); // 0..15

    // A tile load mapping: 128 rows x 8 cols = 1024 floats = 256 threads x float4
    const int aRow = tid / 2;
    const int aCol = (tid % 2) * 4;
    // B tile load mapping: 8 rows x 128 cols
    const int bRow = tid / 32;
    const int bCol = (tid % 32) * 4;

    float acc[TM][TN];
#pragma unroll
    for (int i = 0; i < TM; i++)
#pragma unroll
        for (int j = 0; j < TN; j++) acc[i][j] = 0.f;

    for (int k0 = 0; k0 < K; k0 += BK) {
        // load A (transposed into As), guard M
        const int gr = brow * BM + aRow;
        float4 av = make_float4(0.f, 0.f, 0.f, 0.f);
        if (gr < M)
            av = *reinterpret_cast<const float4*>(&A[(size_t)gr * K + k0 + aCol]);
        As[aCol + 0][aRow] = av.x;
        As[aCol + 1][aRow] = av.y;
        As[aCol + 2][aRow] = av.z;
        As[aCol + 3][aRow] = av.w;
        // load B (N, K both multiples of tile dims for DIM=768)
        float4 bv = *reinterpret_cast<const float4*>(
            &B[(size_t)(k0 + bRow) * N + bcol * BN + bCol]);
        *reinterpret_cast<float4*>(&Bs[bRow][bCol]) = bv;
        __syncthreads();

#pragma unroll
        for (int k = 0; k < BK; k++) {
            float regA[TM], regB[TN];
#pragma unroll
            for (int i = 0; i < TM; i++) regA[i] = As[k][trow * TM + i];
#pragma unroll
            for (int j = 0; j < TN; j++) regB[j] = Bs[k][tcol * TN + j];
#pragma unroll
            for (int i = 0; i < TM; i++)
#pragma unroll
                for (int j = 0; j < TN; j++) acc[i][j] += regA[i] * regB[j];
        }
        __syncthreads();
    }

#pragma unroll
    for (int i = 0; i < TM; i++) {
        const int r = brow * BM + trow * TM + i;
        if (r >= M) continue;
        float* crow = &C[(size_t)r * N + bcol * BN + tcol * TN];
#pragma unroll
        for (int j = 0; j < TN; j += 4) {
            float4 v = make_float4(acc[i][j], acc[i][j + 1], acc[i][j + 2], acc[i][j + 3]);
            *reinterpret_cast<float4*>(&crow[j]) = v;
        }
    }
}

// ---------------- per-node attention dot products ----------------
__global__ void attn_dots(const float* __restrict__ h,
                          const float* __restrict__ asrc,
                          const float* __restrict__ adst,
                          float* __restrict__ as_out,
                          float* __restrict__ ad_out, int n) {
    const int warp = (blockIdx.x * blockDim.x + threadIdx.x) >> 5;
    const int lane = threadIdx.x & 31;
    if (warp >= n) return;
    const float* row = h + (size_t)warp * DIM;
    float s1 = 0.f, s2 = 0.f;
#pragma unroll
    for (int i = 0; i < DIM / 32; i++) {
        const float v = row[lane + 32 * i];
        s1 += v * asrc[lane + 32 * i];
        s2 += v * adst[lane + 32 * i];
    }
#pragma unroll
    for (int o = 16; o; o >>= 1) {
        s1 += __shfl_down_sync(0xffffffffu, s1, o);
        s2 += __shfl_down_sync(0xffffffffu, s2, o);
    }
    if (lane == 0) { as_out[warp] = s1; ad_out[warp] = s2; }
}

// ---------------- init kernels ----------------
__global__ void init_nodes(float* __restrict__ m, float* __restrict__ den, int n) {
    const int i = blockIdx.x * blockDim.x + threadIdx.x;
    if (i < n) { m[i] = -INFINITY; den[i] = 0.f; }
}

__global__ void init_out(float* __restrict__ out, const float* __restrict__ bias, int total) {
    const int i = blockIdx.x * blockDim.x + threadIdx.x;
    if (i < total) out[i] = bias[i % DIM];
}

// ---------------- edge passes ----------------
// edge_index is int32: JAX with default x64-disabled config silently produces
// int32 even when the reference asks for int64.
__global__ void edge_logit_max(const int* __restrict__ ei, int n_edges, int n_nodes,
                               const float* __restrict__ as_, const float* __restrict__ ad_,
                               float* __restrict__ e_out, float* __restrict__ m) {
    const int e = blockIdx.x * blockDim.x + threadIdx.x;
    const int tot = n_edges + n_nodes;
    if (e >= tot) return;
    int s, d;
    if (e < n_edges) { s = ei[e]; d = ei[n_edges + e]; }
    else             { s = d = e - n_edges; }
    float v = as_[s] + ad_[d];
    v = v > 0.f ? v : 0.2f * v;   // leaky relu, PyG default slope
    e_out[e] = v;
    atomicMaxF(&m[d], v);
}

__global__ void edge_exp_sum(const int* __restrict__ ei, int n_edges, int n_nodes,
                             float* __restrict__ e_io, const float* __restrict__ m,
                             float* __restrict__ den) {
    const int e = blockIdx.x * blockDim.x + threadIdx.x;
    const int tot = n_edges + n_nodes;
    if (e >= tot) return;
    int d;
    if (e < n_edges) d = ei[n_edges + e];
    else             d = e - n_edges;
    const float ee = __expf(e_io[e] - m[d]);
    e_io[e] = ee;
    atomicAdd(&den[d], ee);
}

// one warp per edge: out[dst] += alpha * h[src]
__global__ void edge_scatter(const int* __restrict__ ei, int n_edges, int n_nodes,
                             const float* __restrict__ e_exp, const float* __restrict__ den,
                             const float* __restrict__ h, float* __restrict__ out) {
    const int warps_per_block = blockDim.x >> 5;
    const int e = blockIdx.x * warps_per_block + (threadIdx.x >> 5);
    const int lane = threadIdx.x & 31;
    const int tot = n_edges + n_nodes;
    if (e >= tot) return;
    int s, d;
    if (e < n_edges) { s = ei[e]; d = ei[n_edges + e]; }
    else             { s = d = e - n_edges; }
    const float alpha = e_exp[e] / den[d];
    const float4* hrow = reinterpret_cast<const float4*>(h + (size_t)s * DIM);
    float* orow = out + (size_t)d * DIM;
#pragma unroll
    for (int i = 0; i < DIM / 128; i++) {   // 6 iterations: 32 lanes x float4
        const int idx = lane + 32 * i;
        const float4 v = hrow[idx];
        const int base = idx * 4;
        atomicAdd(&orow[base + 0], alpha * v.x);
        atomicAdd(&orow[base + 1], alpha * v.y);
        atomicAdd(&orow[base + 2], alpha * v.z);
        atomicAdd(&orow[base + 3], alpha * v.w);
    }
}

__global__ void relu_k(float* __restrict__ x, int total) {
    const int i = blockIdx.x * blockDim.x + threadIdx.x;
    if (i < total) x[i] = fmaxf(x[i], 0.f);
}

// ---------------- launch ----------------
extern "C" void kernel_launch(void* const* d_in, const int* in_sizes, int n_in,
                              void* d_out, int out_size) {
    const float* x    = (const float*)d_in[0];
    const int*   ei   = (const int*)d_in[1];     // int32 edge_index [2, E]
    const float* W1   = (const float*)d_in[2];
    const float* as1  = (const float*)d_in[3];
    const float* ad1  = (const float*)d_in[4];
    const float* b1   = (const float*)d_in[5];
    const float* W2   = (const float*)d_in[6];
    const float* as2  = (const float*)d_in[7];
    const float* ad2  = (const float*)d_in[8];
    const float* b2   = (const float*)d_in[9];

    const int n_nodes = in_sizes[0] / DIM;
    const int n_edges = in_sizes[1] / 2;
    const int tot     = n_edges + n_nodes;

    float *h, *x1, *as_, *ad_, *m, *den, *e;
    cudaGetSymbolAddress((void**)&h,   g_h);
    cudaGetSymbolAddress((void**)&x1,  g_x1);
    cudaGetSymbolAddress((void**)&as_, g_as);
    cudaGetSymbolAddress((void**)&ad_, g_ad);
    cudaGetSymbolAddress((void**)&m,   g_m);
    cudaGetSymbolAddress((void**)&den, g_den);
    cudaGetSymbolAddress((void**)&e,   g_e);

    const dim3 gemm_grid(DIM / 128, (n_nodes + 127) / 128);
    const int  nd_total = n_nodes * DIM;

    // ---------------- layer 1 ----------------
    sgemm128<<<gemm_grid, 256>>>(n_nodes, DIM, DIM, x, W1, h);
    attn_dots<<<(n_nodes + 3) / 4, 128>>>(h, as1, ad1, as_, ad_, n_nodes);
    init_nodes<<<(n_nodes + 255) / 256, 256>>>(m, den, n_nodes);
    init_out<<<(nd_total + 255) / 256, 256>>>(x1, b1, nd_total);
    edge_logit_max<<<(tot + 255) / 256, 256>>>(ei, n_edges, n_nodes, as_, ad_, e, m);
    edge_exp_sum<<<(tot + 255) / 256, 256>>>(ei, n_edges, n_nodes, e, m, den);
    edge_scatter<<<(tot + 7) / 8, 256>>>(ei, n_edges, n_nodes, e, den, h, x1);
    relu_k<<<(nd_total + 255) / 256, 256>>>(x1, nd_total);

    // ---------------- layer 2 ----------------
    sgemm128<<<gemm_grid, 256>>>(n_nodes, DIM, DIM, x1, W2, h);
    attn_dots<<<(n_nodes + 3) / 4, 128>>>(h, as2, ad2, as_, ad_, n_nodes);
    init_nodes<<<(n_nodes + 255) / 256, 256>>>(m, den, n_nodes);
    init_out<<<(nd_total + 255) / 256, 256>>>((float*)d_out, b2, nd_total);
    edge_logit_max<<<(tot + 255) / 256, 256>>>(ei, n_edges, n_nodes, as_, ad_, e, m);
    edge_exp_sum<<<(tot + 255) / 256, 256>>>(ei, n_edges, n_nodes, e, m, den);
    edge_scatter<<<(tot + 7) / 8, 256>>>(ei, n_edges, n_nodes, e, den, h, (float*)d_out);
}

// round 4
// speedup vs baseline: 1.3335x; 1.3335x over previous
#include <cuda_runtime.h>
#include <math.h>

#define DIM   768
#define MAXN  10000
#define MAXE  100000

// ---------------- scratch (static device globals; no allocation) ----------------
__device__ float g_h [MAXN * DIM];     // h = x @ W (per-layer, reused)
__device__ float g_x1[MAXN * DIM];     // layer-1 output (relu'd) = layer-2 input
__device__ float g_as[MAXN];
__device__ float g_ad[MAXN];
__device__ int   g_cnt[MAXN];          // in-degree histogram
__device__ int   g_rowptr[MAXN + 1];   // CSR row pointers (by dst)
__device__ int   g_cursor[MAXN];       // fill cursors
__device__ int   g_srcs[MAXE + MAXN];  // src node per CSR-sorted edge

// ---------------- packed fp32x2 FMA (sm_103a FFMA2) ----------------
__device__ __forceinline__ void ffma2(unsigned long long& d,
                                      unsigned long long a,
                                      unsigned long long b) {
    asm("fma.rn.f32x2 %0, %1, %2, %0;" : "+l"(d) : "l"(a), "l"(b));
}

// ---------------- SGEMM: C[MxN] = A[MxK] @ B[KxN], row-major ----------------
// BM=128, BN=128, BK=8, 8x8 per thread, 256 threads.
// A tile stored DUPLICATED in shared as float2 (a,a) so the FFMA2 broadcast
// operand comes straight from LDS.128 (no per-k packing MOVs).
__global__ __launch_bounds__(256) void sgemm128(int M, int N, int K,
                         const float* __restrict__ A,
                         const float* __restrict__ B,
                         float* __restrict__ C) {
    const int BM = 128, BN = 128, BK = 8, TM = 8, TN = 8;
    __shared__ float2 As2[BK][BM];   // 8 KB, duplicated A values
    __shared__ float  Bs [BK][BN];   // 4 KB

    const int bcol = blockIdx.x;      // N tile
    const int brow = blockIdx.y;      // M tile
    const int tid  = threadIdx.x;     // 0..255

    const int trow = tid / (BN / TN); // 0..15
    const int tcol = tid % (BN / TN); // 0..15

    const int aRow = tid / 2;
    const int aCol = (tid % 2) * 4;
    const int bRow = tid / 32;
    const int bCol = (tid % 32) * 4;

    unsigned long long acc2[TM][TN / 2] = {};   // (c[i][2j], c[i][2j+1]) pairs

    for (int k0 = 0; k0 < K; k0 += BK) {
        const int gr = brow * BM + aRow;
        float4 av = make_float4(0.f, 0.f, 0.f, 0.f);
        if (gr < M)
            av = *reinterpret_cast<const float4*>(&A[(size_t)gr * K + k0 + aCol]);
        As2[aCol + 0][aRow] = make_float2(av.x, av.x);
        As2[aCol + 1][aRow] = make_float2(av.y, av.y);
        As2[aCol + 2][aRow] = make_float2(av.z, av.z);
        As2[aCol + 3][aRow] = make_float2(av.w, av.w);
        float4 bv = *reinterpret_cast<const float4*>(
            &B[(size_t)(k0 + bRow) * N + bcol * BN + bCol]);
        *reinterpret_cast<float4*>(&Bs[bRow][bCol]) = bv;
        __syncthreads();

#pragma unroll
        for (int k = 0; k < BK; k++) {
            const ulonglong2* aP =
                reinterpret_cast<const ulonglong2*>(&As2[k][trow * TM]);
            ulonglong2 a01 = aP[0], a23 = aP[1], a45 = aP[2], a67 = aP[3];
            unsigned long long a2[TM] = {a01.x, a01.y, a23.x, a23.y,
                                         a45.x, a45.y, a67.x, a67.y};
            const ulonglong2* bP =
                reinterpret_cast<const ulonglong2*>(&Bs[k][tcol * TN]);
            ulonglong2 b01 = bP[0], b23 = bP[1];
            unsigned long long b2[TN / 2] = {b01.x, b01.y, b23.x, b23.y};
#pragma unroll
            for (int i = 0; i < TM; i++)
#pragma unroll
                for (int j = 0; j < TN / 2; j++)
                    ffma2(acc2[i][j], a2[i], b2[j]);
        }
        __syncthreads();
    }

#pragma unroll
    for (int i = 0; i < TM; i++) {
        const int r = brow * BM + trow * TM + i;
        if (r >= M) continue;
        float* crow = &C[(size_t)r * N + bcol * BN + tcol * TN];
#pragma unroll
        for (int j = 0; j < TN / 2; j += 2) {
            float2 p0 = *reinterpret_cast<float2*>(&acc2[i][j]);
            float2 p1 = *reinterpret_cast<float2*>(&acc2[i][j + 1]);
            float4 v = make_float4(p0.x, p0.y, p1.x, p1.y);
            *reinterpret_cast<float4*>(&crow[j * 2]) = v;
        }
    }
}

// ---------------- per-node attention dot products ----------------
__global__ void attn_dots(const float* __restrict__ h,
                          const float* __restrict__ asrc,
                          const float* __restrict__ adst,
                          float* __restrict__ as_out,
                          float* __restrict__ ad_out, int n) {
    const int warp = (blockIdx.x * blockDim.x + threadIdx.x) >> 5;
    const int lane = threadIdx.x & 31;
    if (warp >= n) return;
    const float* row = h + (size_t)warp * DIM;
    float s1 = 0.f, s2 = 0.f;
#pragma unroll
    for (int i = 0; i < DIM / 32; i++) {
        const float v = row[lane + 32 * i];
        s1 += v * asrc[lane + 32 * i];
        s2 += v * adst[lane + 32 * i];
    }
#pragma unroll
    for (int o = 16; o; o >>= 1) {
        s1 += __shfl_down_sync(0xffffffffu, s1, o);
        s2 += __shfl_down_sync(0xffffffffu, s2, o);
    }
    if (lane == 0) { as_out[warp] = s1; ad_out[warp] = s2; }
}

// ---------------- CSR build (once per launch, shared by both layers) --------
__global__ void zero_cnt(int* __restrict__ cnt, int n) {
    const int i = blockIdx.x * blockDim.x + threadIdx.x;
    if (i < n) cnt[i] = 0;
}

__global__ void hist_k(const int* __restrict__ ei, int nE, int nN,
                       int* __restrict__ cnt) {
    const int e = blockIdx.x * blockDim.x + threadIdx.x;
    if (e >= nE + nN) return;
    const int d = (e < nE) ? ei[nE + e] : (e - nE);
    atomicAdd(&cnt[d], 1);
}

// single-block exclusive scan over n counts -> rowptr[0..n], cursor copy
__global__ void scan_rowptr(const int* __restrict__ cnt, int* __restrict__ rowptr,
                            int* __restrict__ cursor, int n) {
    __shared__ int sh[32];
    __shared__ int carry_sh;
    const int tid = threadIdx.x, lane = tid & 31, wid = tid >> 5;
    if (tid == 0) carry_sh = 0;
    __syncthreads();
    for (int base = 0; base < n; base += 1024) {
        const int i = base + tid;
        const int v = (i < n) ? cnt[i] : 0;
        int x = v;
#pragma unroll
        for (int o = 1; o < 32; o <<= 1) {
            int y = __shfl_up_sync(0xffffffffu, x, o);
            if (lane >= o) x += y;
        }
        if (lane == 31) sh[wid] = x;
        __syncthreads();
        if (wid == 0) {
            int s = sh[lane];
#pragma unroll
            for (int o = 1; o < 32; o <<= 1) {
                int y = __shfl_up_sync(0xffffffffu, s, o);
                if (lane >= o) s += y;
            }
            sh[lane] = s;
        }
        __syncthreads();
        const int incl = x + (wid > 0 ? sh[wid - 1] : 0);
        const int carry = carry_sh;
        if (i < n) {
            rowptr[i] = carry + incl - v;
            cursor[i] = carry + incl - v;
        }
        __syncthreads();
        if (tid == 1023) carry_sh = carry + incl;
        __syncthreads();
    }
    if (threadIdx.x == 0) rowptr[n] = carry_sh;
}

__global__ void fill_csr(const int* __restrict__ ei, int nE, int nN,
                         int* __restrict__ cursor, int* __restrict__ srcs) {
    const int e = blockIdx.x * blockDim.x + threadIdx.x;
    if (e >= nE + nN) return;
    int s, d;
    if (e < nE) { s = ei[e]; d = ei[nE + e]; }
    else        { s = d = e - nE; }
    const int pos = atomicAdd(&cursor[d], 1);
    srcs[pos] = s;
}

// ---------------- fused per-node softmax + gather aggregation ----------------
// one warp per destination node: segment max, exp-sum, then
// out[node] = sum_j alpha_j * h[src_j] + bias  (optional relu)
__global__ void gat_gather(const int* __restrict__ rowptr, const int* __restrict__ srcs,
                           const float* __restrict__ as_, const float* __restrict__ ad_,
                           const float* __restrict__ h, const float* __restrict__ bias,
                           float* __restrict__ out, int n, int do_relu) {
    const int node = blockIdx.x * (blockDim.x >> 5) + (threadIdx.x >> 5);
    const int lane = threadIdx.x & 31;
    if (node >= n) return;
    const int beg = rowptr[node], end = rowptr[node + 1];
    const float adn = ad_[node];

    // pass 1: segment max of leaky-relu logits
    float mx = -INFINITY;
    for (int j = beg + lane; j < end; j += 32) {
        float v = as_[srcs[j]] + adn;
        v = v > 0.f ? v : 0.2f * v;
        mx = fmaxf(mx, v);
    }
#pragma unroll
    for (int o = 16; o; o >>= 1) mx = fmaxf(mx, __shfl_xor_sync(0xffffffffu, mx, o));

    // pass 2: denominator
    float den = 0.f;
    for (int j = beg + lane; j < end; j += 32) {
        float v = as_[srcs[j]] + adn;
        v = v > 0.f ? v : 0.2f * v;
        den += expf(v - mx);
    }
#pragma unroll
    for (int o = 16; o; o >>= 1) den += __shfl_xor_sync(0xffffffffu, den, o);
    const float inv = 1.f / den;

    // pass 3: weighted gather
    float4 acc[DIM / 128];
#pragma unroll
    for (int q = 0; q < DIM / 128; q++) acc[q] = make_float4(0.f, 0.f, 0.f, 0.f);

    for (int j0 = beg; j0 < end; j0 += 32) {
        const int j = j0 + lane;
        float w = 0.f; int s = 0;
        if (j < end) {
            s = srcs[j];
            float v = as_[s] + adn;
            v = v > 0.f ? v : 0.2f * v;
            w = expf(v - mx) * inv;
        }
        const int cnt = min(32, end - j0);
        for (int t = 0; t < cnt; t++) {
            const float wt = __shfl_sync(0xffffffffu, w, t);
            const int   st = __shfl_sync(0xffffffffu, s, t);
            const float4* hr = reinterpret_cast<const float4*>(h + (size_t)st * DIM);
#pragma unroll
            for (int q = 0; q < DIM / 128; q++) {
                const float4 v = hr[lane + 32 * q];
                acc[q].x += wt * v.x; acc[q].y += wt * v.y;
                acc[q].z += wt * v.z; acc[q].w += wt * v.w;
            }
        }
    }

    const float4* b4 = reinterpret_cast<const float4*>(bias);
    float4* o4 = reinterpret_cast<float4*>(out + (size_t)node * DIM);
#pragma unroll
    for (int q = 0; q < DIM / 128; q++) {
        const float4 bv = b4[lane + 32 * q];
        float4 r = make_float4(acc[q].x + bv.x, acc[q].y + bv.y,
                               acc[q].z + bv.z, acc[q].w + bv.w);
        if (do_relu) {
            r.x = fmaxf(r.x, 0.f); r.y = fmaxf(r.y, 0.f);
            r.z = fmaxf(r.z, 0.f); r.w = fmaxf(r.w, 0.f);
        }
        o4[lane + 32 * q] = r;
    }
}

// ---------------- launch ----------------
extern "C" void kernel_launch(void* const* d_in, const int* in_sizes, int n_in,
                              void* d_out, int out_size) {
    const float* x    = (const float*)d_in[0];
    const int*   ei   = (const int*)d_in[1];     // int32 edge_index [2, E]
    const float* W1   = (const float*)d_in[2];
    const float* as1  = (const float*)d_in[3];
    const float* ad1  = (const float*)d_in[4];
    const float* b1   = (const float*)d_in[5];
    const float* W2   = (const float*)d_in[6];
    const float* as2  = (const float*)d_in[7];
    const float* ad2  = (const float*)d_in[8];
    const float* b2   = (const float*)d_in[9];

    const int n_nodes = in_sizes[0] / DIM;
    const int n_edges = in_sizes[1] / 2;
    const int tot     = n_edges + n_nodes;

    float *h, *x1, *as_, *ad_;
    int *cnt, *rowptr, *cursor, *srcs;
    cudaGetSymbolAddress((void**)&h,      g_h);
    cudaGetSymbolAddress((void**)&x1,     g_x1);
    cudaGetSymbolAddress((void**)&as_,    g_as);
    cudaGetSymbolAddress((void**)&ad_,    g_ad);
    cudaGetSymbolAddress((void**)&cnt,    g_cnt);
    cudaGetSymbolAddress((void**)&rowptr, g_rowptr);
    cudaGetSymbolAddress((void**)&cursor, g_cursor);
    cudaGetSymbolAddress((void**)&srcs,   g_srcs);

    const dim3 gemm_grid(DIM / 128, (n_nodes + 127) / 128);

    // CSR build (shared by both layers)
    zero_cnt<<<(n_nodes + 255) / 256, 256>>>(cnt, n_nodes);
    hist_k<<<(tot + 255) / 256, 256>>>(ei, n_edges, n_nodes, cnt);
    scan_rowptr<<<1, 1024>>>(cnt, rowptr, cursor, n_nodes);
    fill_csr<<<(tot + 255) / 256, 256>>>(ei, n_edges, n_nodes, cursor, srcs);

    // ---------------- layer 1 ----------------
    sgemm128<<<gemm_grid, 256>>>(n_nodes, DIM, DIM, x, W1, h);
    attn_dots<<<(n_nodes + 3) / 4, 128>>>(h, as1, ad1, as_, ad_, n_nodes);
    gat_gather<<<(n_nodes + 7) / 8, 256>>>(rowptr, srcs, as_, ad_, h, b1, x1,
                                           n_nodes, 1);

    // ---------------- layer 2 ----------------
    sgemm128<<<gemm_grid, 256>>>(n_nodes, DIM, DIM, x1, W2, h);
    attn_dots<<<(n_nodes + 3) / 4, 128>>>(h, as2, ad2, as_, ad_, n_nodes);
    gat_gather<<<(n_nodes + 7) / 8, 256>>>(rowptr, srcs, as_, ad_, h, b2,
                                           (float*)d_out, n_nodes, 0);
}

// round 6
// speedup vs baseline: 2.8562x; 2.1419x over previous
#include <cuda_runtime.h>
#include <cuda_bf16.h>
#include <math.h>
#include <stdint.h>

#define DIM   768
#define MAXN  10000
#define MAXE  100000

// ---------------- scratch (static device globals; no allocation) ----------------
__device__ float g_h [MAXN * DIM];     // h = x @ W (per-layer, reused)
__device__ float g_x1[MAXN * DIM];     // layer-1 output (relu'd) = layer-2 input
__device__ float g_as[MAXN];
__device__ float g_ad[MAXN];
__device__ int   g_cnt[MAXN];
__device__ int   g_rowptr[MAXN + 1];
__device__ int   g_cursor[MAXN];
__device__ int   g_srcs[MAXE + MAXN];
// bf16 split operands
__device__ __nv_bfloat16 g_ah[MAXN * DIM];
__device__ __nv_bfloat16 g_al[MAXN * DIM];
__device__ __nv_bfloat16 g_w1h[DIM * DIM], g_w1l[DIM * DIM];   // W1^T split
__device__ __nv_bfloat16 g_w2h[DIM * DIM], g_w2l[DIM * DIM];   // W2^T split

// ---------------- mma.sync helpers (sm_80+ path; valid on plain sm_103) ------
__device__ __forceinline__ void mma_bf16(float* c, const uint32_t* a, const uint32_t* b) {
    asm volatile(
        "mma.sync.aligned.m16n8k16.row.col.f32.bf16.bf16.f32 "
        "{%0,%1,%2,%3}, {%4,%5,%6,%7}, {%8,%9}, {%0,%1,%2,%3};"
        : "+f"(c[0]), "+f"(c[1]), "+f"(c[2]), "+f"(c[3])
        : "r"(a[0]), "r"(a[1]), "r"(a[2]), "r"(a[3]), "r"(b[0]), "r"(b[1]));
}
__device__ __forceinline__ void ldm4(uint32_t* r, const __nv_bfloat16* p) {
    const uint32_t addr = (uint32_t)__cvta_generic_to_shared(p);
    asm volatile("ldmatrix.sync.aligned.m8n8.x4.shared.b16 {%0,%1,%2,%3}, [%4];"
                 : "=r"(r[0]), "=r"(r[1]), "=r"(r[2]), "=r"(r[3]) : "r"(addr));
}

// ---------------- tensor-core GEMM: C[MxDIM] = A[MxDIM] @ Wt^T ----------------
// A as bf16 hi/lo [M][K]; Wt as bf16 hi/lo [N][K]. 2-term split:
// C = Ah*Bh + Ah*Bl + Al*Bh (fp32 accum). BM=BN=128, BK=32, 8 warps (2x4).
#define LDSS 40   // smem row stride in bf16 (32 data + 8 pad = 80B, 16B-aligned)

__global__ __launch_bounds__(256, 2) void gemm_mma(
        int M,
        const __nv_bfloat16* __restrict__ Ah, const __nv_bfloat16* __restrict__ Al,
        const __nv_bfloat16* __restrict__ Bh, const __nv_bfloat16* __restrict__ Bl,
        float* __restrict__ C) {
    __shared__ __nv_bfloat16 sAh[128 * LDSS], sAl[128 * LDSS];
    __shared__ __nv_bfloat16 sBh[128 * LDSS], sBl[128 * LDSS];

    const int tid  = threadIdx.x;
    const int lane = tid & 31;
    const int warp = tid >> 5;
    const int wm   = warp >> 2;          // 0..1  (64 rows each)
    const int wn   = warp & 3;           // 0..3  (32 cols each)
    const int m0   = blockIdx.y * 128;
    const int n0   = blockIdx.x * 128;
    const int rowsv = min(128, M - m0);

    float acc[4][4][4];
#pragma unroll
    for (int i = 0; i < 4; i++)
#pragma unroll
        for (int j = 0; j < 4; j++)
#pragma unroll
            for (int q = 0; q < 4; q++) acc[i][j][q] = 0.f;

    // ldmatrix source offsets (within warp tile)
    const int amat = lane >> 3, ar = lane & 7;
    const int a_row_off = ((amat & 1) << 3) + ar;      // + mt*16
    const int a_col_off = (amat >> 1) << 3;            // + kc*16
    const int b_row_off = ((amat >> 1) << 3) + ar;     // + p*16
    const int b_col_off = (amat & 1) << 3;             // + kc*16

    for (int k0 = 0; k0 < DIM; k0 += 32) {
        // ---- stage tiles: 512 uint4 per array, 256 threads -> 2 each ----
#pragma unroll
        for (int i = tid; i < 512; i += 256) {
            const int row = i >> 2, seg = (i & 3) * 8;
            const int so = row * LDSS + seg;
            uint4 vah = make_uint4(0, 0, 0, 0), val = vah;
            if (row < rowsv) {
                const size_t ga = (size_t)(m0 + row) * DIM + k0 + seg;
                vah = *reinterpret_cast<const uint4*>(Ah + ga);
                val = *reinterpret_cast<const uint4*>(Al + ga);
            }
            *reinterpret_cast<uint4*>(sAh + so) = vah;
            *reinterpret_cast<uint4*>(sAl + so) = val;
            const size_t gb = (size_t)(n0 + row) * DIM + k0 + seg;
            *reinterpret_cast<uint4*>(sBh + so) = *reinterpret_cast<const uint4*>(Bh + gb);
            *reinterpret_cast<uint4*>(sBl + so) = *reinterpret_cast<const uint4*>(Bl + gb);
        }
        __syncthreads();

#pragma unroll
        for (int kc = 0; kc < 2; kc++) {
            uint32_t ah[4][4], al[4][4];
#pragma unroll
            for (int mt = 0; mt < 4; mt++) {
                const int r = wm * 64 + mt * 16 + a_row_off;
                const int c = kc * 16 + a_col_off;
                ldm4(ah[mt], sAh + r * LDSS + c);
                ldm4(al[mt], sAl + r * LDSS + c);
            }
            uint32_t bh[2][4], bl[2][4];
#pragma unroll
            for (int p = 0; p < 2; p++) {
                const int r = wn * 32 + p * 16 + b_row_off;
                const int c = kc * 16 + b_col_off;
                ldm4(bh[p], sBh + r * LDSS + c);
                ldm4(bl[p], sBl + r * LDSS + c);
            }
#pragma unroll
            for (int mt = 0; mt < 4; mt++)
#pragma unroll
                for (int nt = 0; nt < 4; nt++) {
                    const uint32_t* bhf = &bh[nt >> 1][(nt & 1) * 2];
                    const uint32_t* blf = &bl[nt >> 1][(nt & 1) * 2];
                    mma_bf16(acc[mt][nt], ah[mt], bhf);
                    mma_bf16(acc[mt][nt], ah[mt], blf);
                    mma_bf16(acc[mt][nt], al[mt], bhf);
                }
        }
        __syncthreads();
    }

    // ---- epilogue: direct stores (float2 per reg pair) ----
    const int gr = lane >> 2, gc = (lane & 3) * 2;
#pragma unroll
    for (int mt = 0; mt < 4; mt++) {
#pragma unroll
        for (int nt = 0; nt < 4; nt++) {
            const int m = m0 + wm * 64 + mt * 16 + gr;
            const int n = n0 + wn * 32 + nt * 8 + gc;
            if (m < M)
                *reinterpret_cast<float2*>(&C[(size_t)m * DIM + n]) =
                    make_float2(acc[mt][nt][0], acc[mt][nt][1]);
            if (m + 8 < M)
                *reinterpret_cast<float2*>(&C[(size_t)(m + 8) * DIM + n]) =
                    make_float2(acc[mt][nt][2], acc[mt][nt][3]);
        }
    }
}

// ---------------- bf16 split conversions ----------------
__global__ void split_x(const float* __restrict__ x, __nv_bfloat16* __restrict__ hi,
                        __nv_bfloat16* __restrict__ lo, int total) {
    const int i = blockIdx.x * blockDim.x + threadIdx.x;
    if (i >= total) return;
    const float v = x[i];
    const __nv_bfloat16 h = __float2bfloat16(v);
    hi[i] = h;
    lo[i] = __float2bfloat16(v - __bfloat162float(h));
}

// W [K][N] row-major -> Wt hi/lo [N][K]
__global__ void split_wT(const float* __restrict__ W,
                         __nv_bfloat16* __restrict__ hiT,
                         __nv_bfloat16* __restrict__ loT) {
    __shared__ float t[32][33];
    const int bx = blockIdx.x * 32, by = blockIdx.y * 32;
    const int tx = threadIdx.x, ty = threadIdx.y;
    #pragma unroll
    for (int j = 0; j < 4; j++)
        t[ty + j * 8][tx] = W[(size_t)(by + ty + j * 8) * DIM + bx + tx];
    __syncthreads();
    #pragma unroll
    for (int j = 0; j < 4; j++) {
        const float v = t[tx][ty + j * 8];
        const __nv_bfloat16 h = __float2bfloat16(v);
        const size_t o = (size_t)(bx + ty + j * 8) * DIM + by + tx;
        hiT[o] = h;
        loT[o] = __float2bfloat16(v - __bfloat162float(h));
    }
}

// ---------------- per-node attention dot products ----------------
__global__ void attn_dots(const float* __restrict__ h,
                          const float* __restrict__ asrc,
                          const float* __restrict__ adst,
                          float* __restrict__ as_out,
                          float* __restrict__ ad_out, int n) {
    const int warp = (blockIdx.x * blockDim.x + threadIdx.x) >> 5;
    const int lane = threadIdx.x & 31;
    if (warp >= n) return;
    const float* row = h + (size_t)warp * DIM;
    float s1 = 0.f, s2 = 0.f;
#pragma unroll
    for (int i = 0; i < DIM / 32; i++) {
        const float v = row[lane + 32 * i];
        s1 += v * asrc[lane + 32 * i];
        s2 += v * adst[lane + 32 * i];
    }
#pragma unroll
    for (int o = 16; o; o >>= 1) {
        s1 += __shfl_down_sync(0xffffffffu, s1, o);
        s2 += __shfl_down_sync(0xffffffffu, s2, o);
    }
    if (lane == 0) { as_out[warp] = s1; ad_out[warp] = s2; }
}

// ---------------- CSR build ----------------
__global__ void zero_cnt(int* __restrict__ cnt, int n) {
    const int i = blockIdx.x * blockDim.x + threadIdx.x;
    if (i < n) cnt[i] = 0;
}
__global__ void hist_k(const int* __restrict__ ei, int nE, int nN, int* __restrict__ cnt) {
    const int e = blockIdx.x * blockDim.x + threadIdx.x;
    if (e >= nE + nN) return;
    const int d = (e < nE) ? ei[nE + e] : (e - nE);
    atomicAdd(&cnt[d], 1);
}
__global__ void scan_rowptr(const int* __restrict__ cnt, int* __restrict__ rowptr,
                            int* __restrict__ cursor, int n) {
    __shared__ int sh[32];
    __shared__ int carry_sh;
    const int tid = threadIdx.x, lane = tid & 31, wid = tid >> 5;
    if (tid == 0) carry_sh = 0;
    __syncthreads();
    for (int base = 0; base < n; base += 1024) {
        const int i = base + tid;
        const int v = (i < n) ? cnt[i] : 0;
        int x = v;
#pragma unroll
        for (int o = 1; o < 32; o <<= 1) {
            int y = __shfl_up_sync(0xffffffffu, x, o);
            if (lane >= o) x += y;
        }
        if (lane == 31) sh[wid] = x;
        __syncthreads();
        if (wid == 0) {
            int s = sh[lane];
#pragma unroll
            for (int o = 1; o < 32; o <<= 1) {
                int y = __shfl_up_sync(0xffffffffu, s, o);
                if (lane >= o) s += y;
            }
            sh[lane] = s;
        }
        __syncthreads();
        const int incl = x + (wid > 0 ? sh[wid - 1] : 0);
        const int carry = carry_sh;
        if (i < n) { rowptr[i] = carry + incl - v; cursor[i] = carry + incl - v; }
        __syncthreads();
        if (tid == 1023) carry_sh = carry + incl;
        __syncthreads();
    }
    if (threadIdx.x == 0) rowptr[n] = carry_sh;
}
__global__ void fill_csr(const int* __restrict__ ei, int nE, int nN,
                         int* __restrict__ cursor, int* __restrict__ srcs) {
    const int e = blockIdx.x * blockDim.x + threadIdx.x;
    if (e >= nE + nN) return;
    int s, d;
    if (e < nE) { s = ei[e]; d = ei[nE + e]; }
    else        { s = d = e - nE; }
    const int pos = atomicAdd(&cursor[d], 1);
    srcs[pos] = s;
}

// ---------------- fused per-node softmax + gather ----------------
__global__ void gat_gather(const int* __restrict__ rowptr, const int* __restrict__ srcs,
                           const float* __restrict__ as_, const float* __restrict__ ad_,
                           const float* __restrict__ h, const float* __restrict__ bias,
                           float* __restrict__ out, int n, int do_relu) {
    const int node = blockIdx.x * (blockDim.x >> 5) + (threadIdx.x >> 5);
    const int lane = threadIdx.x & 31;
    if (node >= n) return;
    const int beg = rowptr[node], end = rowptr[node + 1];
    const float adn = ad_[node];

    float mx = -INFINITY;
    for (int j = beg + lane; j < end; j += 32) {
        float v = as_[srcs[j]] + adn;
        v = v > 0.f ? v : 0.2f * v;
        mx = fmaxf(mx, v);
    }
#pragma unroll
    for (int o = 16; o; o >>= 1) mx = fmaxf(mx, __shfl_xor_sync(0xffffffffu, mx, o));

    float den = 0.f;
    for (int j = beg + lane; j < end; j += 32) {
        float v = as_[srcs[j]] + adn;
        v = v > 0.f ? v : 0.2f * v;
        den += expf(v - mx);
    }
#pragma unroll
    for (int o = 16; o; o >>= 1) den += __shfl_xor_sync(0xffffffffu, den, o);
    const float inv = 1.f / den;

    float4 acc[DIM / 128];
#pragma unroll
    for (int q = 0; q < DIM / 128; q++) acc[q] = make_float4(0.f, 0.f, 0.f, 0.f);

    for (int j0 = beg; j0 < end; j0 += 32) {
        const int j = j0 + lane;
        float w = 0.f; int s = 0;
        if (j < end) {
            s = srcs[j];
            float v = as_[s] + adn;
            v = v > 0.f ? v : 0.2f * v;
            w = expf(v - mx) * inv;
        }
        const int cnt = min(32, end - j0);
        for (int t = 0; t < cnt; t++) {
            const float wt = __shfl_sync(0xffffffffu, w, t);
            const int   st = __shfl_sync(0xffffffffu, s, t);
            const float4* hr = reinterpret_cast<const float4*>(h + (size_t)st * DIM);
#pragma unroll
            for (int q = 0; q < DIM / 128; q++) {
                const float4 v = hr[lane + 32 * q];
                acc[q].x += wt * v.x; acc[q].y += wt * v.y;
                acc[q].z += wt * v.z; acc[q].w += wt * v.w;
            }
        }
    }

    const float4* b4 = reinterpret_cast<const float4*>(bias);
    float4* o4 = reinterpret_cast<float4*>(out + (size_t)node * DIM);
#pragma unroll
    for (int q = 0; q < DIM / 128; q++) {
        const float4 bv = b4[lane + 32 * q];
        float4 r = make_float4(acc[q].x + bv.x, acc[q].y + bv.y,
                               acc[q].z + bv.z, acc[q].w + bv.w);
        if (do_relu) {
            r.x = fmaxf(r.x, 0.f); r.y = fmaxf(r.y, 0.f);
            r.z = fmaxf(r.z, 0.f); r.w = fmaxf(r.w, 0.f);
        }
        o4[lane + 32 * q] = r;
    }
}

// ---------------- launch ----------------
extern "C" void kernel_launch(void* const* d_in, const int* in_sizes, int n_in,
                              void* d_out, int out_size) {
    const float* x    = (const float*)d_in[0];
    const int*   ei   = (const int*)d_in[1];     // int32 edge_index [2, E]
    const float* W1   = (const float*)d_in[2];
    const float* as1  = (const float*)d_in[3];
    const float* ad1  = (const float*)d_in[4];
    const float* b1   = (const float*)d_in[5];
    const float* W2   = (const float*)d_in[6];
    const float* as2  = (const float*)d_in[7];
    const float* ad2  = (const float*)d_in[8];
    const float* b2   = (const float*)d_in[9];

    const int n_nodes = in_sizes[0] / DIM;
    const int n_edges = in_sizes[1] / 2;
    const int tot     = n_edges + n_nodes;

    float *h, *x1, *as_, *ad_;
    int *cnt, *rowptr, *cursor, *srcs;
    __nv_bfloat16 *ah, *al, *w1h, *w1l, *w2h, *w2l;
    cudaGetSymbolAddress((void**)&h,      g_h);
    cudaGetSymbolAddress((void**)&x1,     g_x1);
    cudaGetSymbolAddress((void**)&as_,    g_as);
    cudaGetSymbolAddress((void**)&ad_,    g_ad);
    cudaGetSymbolAddress((void**)&cnt,    g_cnt);
    cudaGetSymbolAddress((void**)&rowptr, g_rowptr);
    cudaGetSymbolAddress((void**)&cursor, g_cursor);
    cudaGetSymbolAddress((void**)&srcs,   g_srcs);
    cudaGetSymbolAddress((void**)&ah,     g_ah);
    cudaGetSymbolAddress((void**)&al,     g_al);
    cudaGetSymbolAddress((void**)&w1h,    g_w1h);
    cudaGetSymbolAddress((void**)&w1l,    g_w1l);
    cudaGetSymbolAddress((void**)&w2h,    g_w2h);
    cudaGetSymbolAddress((void**)&w2l,    g_w2l);

    const int nd_total = n_nodes * DIM;
    const dim3 gemm_grid(DIM / 128, (n_nodes + 127) / 128);
    const dim3 tr_grid(DIM / 32, DIM / 32), tr_blk(32, 8);

    // CSR build (shared by both layers)
    zero_cnt<<<(n_nodes + 255) / 256, 256>>>(cnt, n_nodes);
    hist_k<<<(tot + 255) / 256, 256>>>(ei, n_edges, n_nodes, cnt);
    scan_rowptr<<<1, 1024>>>(cnt, rowptr, cursor, n_nodes);
    fill_csr<<<(tot + 255) / 256, 256>>>(ei, n_edges, n_nodes, cursor, srcs);

    // weight splits (transposed)
    split_wT<<<tr_grid, tr_blk>>>(W1, w1h, w1l);
    split_wT<<<tr_grid, tr_blk>>>(W2, w2h, w2l);

    // ---------------- layer 1 ----------------
    split_x<<<(nd_total + 255) / 256, 256>>>(x, ah, al, nd_total);
    gemm_mma<<<gemm_grid, 256>>>(n_nodes, ah, al, w1h, w1l, h);
    attn_dots<<<(n_nodes + 3) / 4, 128>>>(h, as1, ad1, as_, ad_, n_nodes);
    gat_gather<<<(n_nodes + 7) / 8, 256>>>(rowptr, srcs, as_, ad_, h, b1, x1,
                                           n_nodes, 1);

    // ---------------- layer 2 ----------------
    split_x<<<(nd_total + 255) / 256, 256>>>(x1, ah, al, nd_total);
    gemm_mma<<<gemm_grid, 256>>>(n_nodes, ah, al, w2h, w2l, h);
    attn_dots<<<(n_nodes + 3) / 4, 128>>>(h, as2, ad2, as_, ad_, n_nodes);
    gat_gather<<<(n_nodes + 7) / 8, 256>>>(rowptr, srcs, as_, ad_, h, b2,
                                           (float*)d_out, n_nodes, 0);
}

// round 7
// speedup vs baseline: 2.9310x; 1.0262x over previous
#include <cuda_runtime.h>
#include <cuda_bf16.h>
#include <math.h>
#include <stdint.h>

#define DIM   768
#define MAXN  10000
#define MAXE  100000

// ---------------- scratch (static device globals; no allocation) ----------------
__device__ float g_h [MAXN * DIM];     // h = x @ W (per-layer, reused)
__device__ float g_as[MAXN];
__device__ float g_ad[MAXN];
__device__ int   g_cnt[MAXN];
__device__ int   g_rowptr[MAXN + 1];
__device__ int   g_cursor[MAXN];
__device__ int   g_srcs[MAXE + MAXN];
// bf16 split operands
__device__ __nv_bfloat16 g_ah[MAXN * DIM];
__device__ __nv_bfloat16 g_al[MAXN * DIM];
__device__ __nv_bfloat16 g_w1h[DIM * DIM], g_w1l[DIM * DIM];   // W1^T split
__device__ __nv_bfloat16 g_w2h[DIM * DIM], g_w2l[DIM * DIM];   // W2^T split

// ---------------- mma.sync helpers (sm_80+ path; valid on plain sm_103) ------
__device__ __forceinline__ void mma_bf16(float* c, const uint32_t* a, const uint32_t* b) {
    asm volatile(
        "mma.sync.aligned.m16n8k16.row.col.f32.bf16.bf16.f32 "
        "{%0,%1,%2,%3}, {%4,%5,%6,%7}, {%8,%9}, {%0,%1,%2,%3};"
        : "+f"(c[0]), "+f"(c[1]), "+f"(c[2]), "+f"(c[3])
        : "r"(a[0]), "r"(a[1]), "r"(a[2]), "r"(a[3]), "r"(b[0]), "r"(b[1]));
}
__device__ __forceinline__ void ldm4(uint32_t* r, uint32_t addr) {
    asm volatile("ldmatrix.sync.aligned.m8n8.x4.shared.b16 {%0,%1,%2,%3}, [%4];"
                 : "=r"(r[0]), "=r"(r[1]), "=r"(r[2]), "=r"(r[3]) : "r"(addr));
}
__device__ __forceinline__ void cpa16(uint32_t dst, const void* src, int src_bytes) {
    asm volatile("cp.async.ca.shared.global [%0], [%1], 16, %2;"
                 :: "r"(dst), "l"(src), "r"(src_bytes));
}
__device__ __forceinline__ void cpa_commit() {
    asm volatile("cp.async.commit_group;" ::: "memory");
}
template <int N>
__device__ __forceinline__ void cpa_wait() {
    asm volatile("cp.async.wait_group %0;" :: "n"(N) : "memory");
}

// ---------------- tensor-core GEMM + fused attention dots ----------------
// C = Ah*Bh + Ah*Bl + Al*Bh (fp32 accum). BM=BN=128, BK=32, 8 warps (2x4).
// Double-buffered cp.async staging. Epilogue also accumulates
// as_[m] += C[m,:] . att_s  and  ad_[m] += C[m,:] . att_d  via atomics.
#define LDSS     40                    // smem row stride in bf16 (80 B)
#define SM_ARR   (128 * LDSS * 2)      // 10240 B per array
#define SM_STAGE (SM_ARR * 4)          // 40960 B per stage
#define SM_TOT   (SM_STAGE * 2)        // 81920 B

__global__ __launch_bounds__(256, 2) void gemm_mma(
        int M,
        const __nv_bfloat16* __restrict__ Ah, const __nv_bfloat16* __restrict__ Al,
        const __nv_bfloat16* __restrict__ Bh, const __nv_bfloat16* __restrict__ Bl,
        const float* __restrict__ att_s, const float* __restrict__ att_d,
        float* __restrict__ as_, float* __restrict__ ad_,
        float* __restrict__ C) {
    extern __shared__ char dsm[];
    const uint32_t sb = (uint32_t)__cvta_generic_to_shared(dsm);

    const int tid  = threadIdx.x;
    const int lane = tid & 31;
    const int warp = tid >> 5;
    const int wm   = warp >> 2;          // 0..1  (64 rows each)
    const int wn   = warp & 3;           // 0..3  (32 cols each)
    const int m0   = blockIdx.y * 128;
    const int n0   = blockIdx.x * 128;
    const int rowsv = min(128, M - m0);

    // staging indices: i in [0,512): row=i>>2, 16B chunk (i&3)
    const int srow = tid >> 1;                  // with 256 threads: 2 chunks each
    const int schk0 = (tid & 1) * 2;            // chunks {0,1} or {2,3}

    float acc[4][4][4];
#pragma unroll
    for (int i = 0; i < 4; i++)
#pragma unroll
        for (int j = 0; j < 4; j++)
#pragma unroll
            for (int q = 0; q < 4; q++) acc[i][j][q] = 0.f;

    // ldmatrix source offsets (within warp tile)
    const int amat = lane >> 3, ar = lane & 7;
    const int a_row_off = ((amat & 1) << 3) + ar;
    const int a_col_off = (amat >> 1) << 3;
    const int b_row_off = ((amat >> 1) << 3) + ar;
    const int b_col_off = (amat & 1) << 3;

    const int NT = DIM / 32;

    // ---- stage one k-chunk into buffer s ----
    auto stage = [&](int s, int k0) {
        const uint32_t base = sb + s * SM_STAGE;
        const bool av = srow < rowsv;
        const int arow = av ? (m0 + srow) : m0;
        const int asz  = av ? 16 : 0;
#pragma unroll
        for (int c = 0; c < 2; c++) {
            const int chk = schk0 + c;
            const uint32_t so = (uint32_t)(srow * 80 + chk * 16);
            const size_t ga = (size_t)arow * DIM + k0 + chk * 8;
            const size_t gb = (size_t)(n0 + srow) * DIM + k0 + chk * 8;
            cpa16(base + 0 * SM_ARR + so, Ah + ga, asz);
            cpa16(base + 1 * SM_ARR + so, Al + ga, asz);
            cpa16(base + 2 * SM_ARR + so, Bh + gb, 16);
            cpa16(base + 3 * SM_ARR + so, Bl + gb, 16);
        }
    };

    stage(0, 0);
    cpa_commit();

    for (int it = 0; it < NT; it++) {
        const int buf = it & 1;
        if (it + 1 < NT) { stage(buf ^ 1, (it + 1) * 32); cpa_commit(); cpa_wait<1>(); }
        else             { cpa_wait<0>(); }
        __syncthreads();

        const uint32_t bA = sb + buf * SM_STAGE;
#pragma unroll
        for (int kc = 0; kc < 2; kc++) {
            uint32_t ah[4][4], al[4][4];
#pragma unroll
            for (int mt = 0; mt < 4; mt++) {
                const uint32_t off =
                    (uint32_t)((wm * 64 + mt * 16 + a_row_off) * 80 +
                               (kc * 16 + a_col_off) * 2);
                ldm4(ah[mt], bA + 0 * SM_ARR + off);
                ldm4(al[mt], bA + 1 * SM_ARR + off);
            }
            uint32_t bh[2][4], bl[2][4];
#pragma unroll
            for (int p = 0; p < 2; p++) {
                const uint32_t off =
                    (uint32_t)((wn * 32 + p * 16 + b_row_off) * 80 +
                               (kc * 16 + b_col_off) * 2);
                ldm4(bh[p], bA + 2 * SM_ARR + off);
                ldm4(bl[p], bA + 3 * SM_ARR + off);
            }
#pragma unroll
            for (int mt = 0; mt < 4; mt++)
#pragma unroll
                for (int nt = 0; nt < 4; nt++) {
                    const uint32_t* bhf = &bh[nt >> 1][(nt & 1) * 2];
                    const uint32_t* blf = &bl[nt >> 1][(nt & 1) * 2];
                    mma_bf16(acc[mt][nt], ah[mt], bhf);
                    mma_bf16(acc[mt][nt], ah[mt], blf);
                    mma_bf16(acc[mt][nt], al[mt], bhf);
                }
        }
        __syncthreads();
    }

    // ---- epilogue: store C + fused attention dot partials ----
    const int gr = lane >> 2, gc = (lane & 3) * 2;
#pragma unroll
    for (int mt = 0; mt < 4; mt++) {
        float s0 = 0.f, s1 = 0.f, d0 = 0.f, d1 = 0.f;
#pragma unroll
        for (int nt = 0; nt < 4; nt++) {
            const int m = m0 + wm * 64 + mt * 16 + gr;
            const int n = n0 + wn * 32 + nt * 8 + gc;
            const float2 av = *reinterpret_cast<const float2*>(att_s + n);
            const float2 dv = *reinterpret_cast<const float2*>(att_d + n);
            s0 += acc[mt][nt][0] * av.x + acc[mt][nt][1] * av.y;
            s1 += acc[mt][nt][2] * av.x + acc[mt][nt][3] * av.y;
            d0 += acc[mt][nt][0] * dv.x + acc[mt][nt][1] * dv.y;
            d1 += acc[mt][nt][2] * dv.x + acc[mt][nt][3] * dv.y;
            if (m < M)
                *reinterpret_cast<float2*>(&C[(size_t)m * DIM + n]) =
                    make_float2(acc[mt][nt][0], acc[mt][nt][1]);
            if (m + 8 < M)
                *reinterpret_cast<float2*>(&C[(size_t)(m + 8) * DIM + n]) =
                    make_float2(acc[mt][nt][2], acc[mt][nt][3]);
        }
        // quad butterfly reduce (lanes gr*4 .. gr*4+3 hold same rows)
#pragma unroll
        for (int o = 1; o < 4; o <<= 1) {
            s0 += __shfl_xor_sync(0xffffffffu, s0, o);
            s1 += __shfl_xor_sync(0xffffffffu, s1, o);
            d0 += __shfl_xor_sync(0xffffffffu, d0, o);
            d1 += __shfl_xor_sync(0xffffffffu, d1, o);
        }
        if ((lane & 3) == 0) {
            const int m = m0 + wm * 64 + mt * 16 + gr;
            if (m < M)     { atomicAdd(&as_[m], s0);     atomicAdd(&ad_[m], d0); }
            if (m + 8 < M) { atomicAdd(&as_[m + 8], s1); atomicAdd(&ad_[m + 8], d1); }
        }
    }
}

// ---------------- bf16 split conversions ----------------
__global__ void split_x(const float* __restrict__ x, __nv_bfloat16* __restrict__ hi,
                        __nv_bfloat16* __restrict__ lo, int total) {
    const int i = blockIdx.x * blockDim.x + threadIdx.x;
    if (i >= total) return;
    const float v = x[i];
    const __nv_bfloat16 h = __float2bfloat16(v);
    hi[i] = h;
    lo[i] = __float2bfloat16(v - __bfloat162float(h));
}

// W [K][N] row-major -> Wt hi/lo [N][K]
__global__ void split_wT(const float* __restrict__ W,
                         __nv_bfloat16* __restrict__ hiT,
                         __nv_bfloat16* __restrict__ loT) {
    __shared__ float t[32][33];
    const int bx = blockIdx.x * 32, by = blockIdx.y * 32;
    const int tx = threadIdx.x, ty = threadIdx.y;
    #pragma unroll
    for (int j = 0; j < 4; j++)
        t[ty + j * 8][tx] = W[(size_t)(by + ty + j * 8) * DIM + bx + tx];
    __syncthreads();
    #pragma unroll
    for (int j = 0; j < 4; j++) {
        const float v = t[tx][ty + j * 8];
        const __nv_bfloat16 h = __float2bfloat16(v);
        const size_t o = (size_t)(bx + ty + j * 8) * DIM + by + tx;
        hiT[o] = h;
        loT[o] = __float2bfloat16(v - __bfloat162float(h));
    }
}

__global__ void zero_ad(float* __restrict__ a, float* __restrict__ b, int n) {
    const int i = blockIdx.x * blockDim.x + threadIdx.x;
    if (i < n) { a[i] = 0.f; b[i] = 0.f; }
}

// ---------------- CSR build ----------------
__global__ void zero_cnt(int* __restrict__ cnt, int n) {
    const int i = blockIdx.x * blockDim.x + threadIdx.x;
    if (i < n) cnt[i] = 0;
}
__global__ void hist_k(const int* __restrict__ ei, int nE, int nN, int* __restrict__ cnt) {
    const int e = blockIdx.x * blockDim.x + threadIdx.x;
    if (e >= nE + nN) return;
    const int d = (e < nE) ? ei[nE + e] : (e - nE);
    atomicAdd(&cnt[d], 1);
}
__global__ void scan_rowptr(const int* __restrict__ cnt, int* __restrict__ rowptr,
                            int* __restrict__ cursor, int n) {
    __shared__ int sh[32];
    __shared__ int carry_sh;
    const int tid = threadIdx.x, lane = tid & 31, wid = tid >> 5;
    if (tid == 0) carry_sh = 0;
    __syncthreads();
    for (int base = 0; base < n; base += 1024) {
        const int i = base + tid;
        const int v = (i < n) ? cnt[i] : 0;
        int x = v;
#pragma unroll
        for (int o = 1; o < 32; o <<= 1) {
            int y = __shfl_up_sync(0xffffffffu, x, o);
            if (lane >= o) x += y;
        }
        if (lane == 31) sh[wid] = x;
        __syncthreads();
        if (wid == 0) {
            int s = sh[lane];
#pragma unroll
            for (int o = 1; o < 32; o <<= 1) {
                int y = __shfl_up_sync(0xffffffffu, s, o);
                if (lane >= o) s += y;
            }
            sh[lane] = s;
        }
        __syncthreads();
        const int incl = x + (wid > 0 ? sh[wid - 1] : 0);
        const int carry = carry_sh;
        if (i < n) { rowptr[i] = carry + incl - v; cursor[i] = carry + incl - v; }
        __syncthreads();
        if (tid == 1023) carry_sh = carry + incl;
        __syncthreads();
    }
    if (threadIdx.x == 0) rowptr[n] = carry_sh;
}
__global__ void fill_csr(const int* __restrict__ ei, int nE, int nN,
                         int* __restrict__ cursor, int* __restrict__ srcs) {
    const int e = blockIdx.x * blockDim.x + threadIdx.x;
    if (e >= nE + nN) return;
    int s, d;
    if (e < nE) { s = ei[e]; d = ei[nE + e]; }
    else        { s = d = e - nE; }
    const int pos = atomicAdd(&cursor[d], 1);
    srcs[pos] = s;
}

// ---------------- fused per-node softmax + gather ----------------
// mode 0: write float out (layer 2, no relu)
// mode 1: relu, then write bf16 hi/lo split (layer 1 -> layer 2 GEMM operands)
__global__ void gat_gather(const int* __restrict__ rowptr, const int* __restrict__ srcs,
                           const float* __restrict__ as_, const float* __restrict__ ad_,
                           const float* __restrict__ h, const float* __restrict__ bias,
                           float* __restrict__ outF,
                           __nv_bfloat16* __restrict__ outH,
                           __nv_bfloat16* __restrict__ outL,
                           int n, int mode) {
    const int node = blockIdx.x * (blockDim.x >> 5) + (threadIdx.x >> 5);
    const int lane = threadIdx.x & 31;
    if (node >= n) return;
    const int beg = rowptr[node], end = rowptr[node + 1];
    const float adn = ad_[node];

    float mx = -INFINITY;
    for (int j = beg + lane; j < end; j += 32) {
        float v = as_[srcs[j]] + adn;
        v = v > 0.f ? v : 0.2f * v;
        mx = fmaxf(mx, v);
    }
#pragma unroll
    for (int o = 16; o; o >>= 1) mx = fmaxf(mx, __shfl_xor_sync(0xffffffffu, mx, o));

    float den = 0.f;
    for (int j = beg + lane; j < end; j += 32) {
        float v = as_[srcs[j]] + adn;
        v = v > 0.f ? v : 0.2f * v;
        den += expf(v - mx);
    }
#pragma unroll
    for (int o = 16; o; o >>= 1) den += __shfl_xor_sync(0xffffffffu, den, o);
    const float inv = 1.f / den;

    float4 acc[DIM / 128];
#pragma unroll
    for (int q = 0; q < DIM / 128; q++) acc[q] = make_float4(0.f, 0.f, 0.f, 0.f);

    for (int j0 = beg; j0 < end; j0 += 32) {
        const int j = j0 + lane;
        float w = 0.f; int s = 0;
        if (j < end) {
            s = srcs[j];
            float v = as_[s] + adn;
            v = v > 0.f ? v : 0.2f * v;
            w = expf(v - mx) * inv;
        }
        const int cnt = min(32, end - j0);
        for (int t = 0; t < cnt; t++) {
            const float wt = __shfl_sync(0xffffffffu, w, t);
            const int   st = __shfl_sync(0xffffffffu, s, t);
            const float4* hr = reinterpret_cast<const float4*>(h + (size_t)st * DIM);
#pragma unroll
            for (int q = 0; q < DIM / 128; q++) {
                const float4 v = hr[lane + 32 * q];
                acc[q].x += wt * v.x; acc[q].y += wt * v.y;
                acc[q].z += wt * v.z; acc[q].w += wt * v.w;
            }
        }
    }

    const float4* b4 = reinterpret_cast<const float4*>(bias);
#pragma unroll
    for (int q = 0; q < DIM / 128; q++) {
        const float4 bv = b4[lane + 32 * q];
        float4 r = make_float4(acc[q].x + bv.x, acc[q].y + bv.y,
                               acc[q].z + bv.z, acc[q].w + bv.w);
        if (mode == 1) {
            r.x = fmaxf(r.x, 0.f); r.y = fmaxf(r.y, 0.f);
            r.z = fmaxf(r.z, 0.f); r.w = fmaxf(r.w, 0.f);
            const size_t off = (size_t)node * DIM + (lane + 32 * q) * 4;
            float hx = __bfloat162float(__float2bfloat16(r.x));
            float hy = __bfloat162float(__float2bfloat16(r.y));
            float hz = __bfloat162float(__float2bfloat16(r.z));
            float hw = __bfloat162float(__float2bfloat16(r.w));
            __nv_bfloat162 h01, h23, l01, l23;
            h01 = __nv_bfloat162(__float2bfloat16(r.x), __float2bfloat16(r.y));
            h23 = __nv_bfloat162(__float2bfloat16(r.z), __float2bfloat16(r.w));
            l01 = __nv_bfloat162(__float2bfloat16(r.x - hx), __float2bfloat16(r.y - hy));
            l23 = __nv_bfloat162(__float2bfloat16(r.z - hz), __float2bfloat16(r.w - hw));
            uint2 hp = make_uint2(*(uint32_t*)&h01, *(uint32_t*)&h23);
            uint2 lp = make_uint2(*(uint32_t*)&l01, *(uint32_t*)&l23);
            *reinterpret_cast<uint2*>(outH + off) = hp;
            *reinterpret_cast<uint2*>(outL + off) = lp;
        } else {
            float4* o4 = reinterpret_cast<float4*>(outF + (size_t)node * DIM);
            o4[lane + 32 * q] = r;
        }
    }
}

// ---------------- launch ----------------
extern "C" void kernel_launch(void* const* d_in, const int* in_sizes, int n_in,
                              void* d_out, int out_size) {
    const float* x    = (const float*)d_in[0];
    const int*   ei   = (const int*)d_in[1];     // int32 edge_index [2, E]
    const float* W1   = (const float*)d_in[2];
    const float* as1  = (const float*)d_in[3];
    const float* ad1  = (const float*)d_in[4];
    const float* b1   = (const float*)d_in[5];
    const float* W2   = (const float*)d_in[6];
    const float* as2  = (const float*)d_in[7];
    const float* ad2  = (const float*)d_in[8];
    const float* b2   = (const float*)d_in[9];

    const int n_nodes = in_sizes[0] / DIM;
    const int n_edges = in_sizes[1] / 2;
    const int tot     = n_edges + n_nodes;

    float *h, *as_, *ad_;
    int *cnt, *rowptr, *cursor, *srcs;
    __nv_bfloat16 *ah, *al, *w1h, *w1l, *w2h, *w2l;
    cudaGetSymbolAddress((void**)&h,      g_h);
    cudaGetSymbolAddress((void**)&as_,    g_as);
    cudaGetSymbolAddress((void**)&ad_,    g_ad);
    cudaGetSymbolAddress((void**)&cnt,    g_cnt);
    cudaGetSymbolAddress((void**)&rowptr, g_rowptr);
    cudaGetSymbolAddress((void**)&cursor, g_cursor);
    cudaGetSymbolAddress((void**)&srcs,   g_srcs);
    cudaGetSymbolAddress((void**)&ah,     g_ah);
    cudaGetSymbolAddress((void**)&al,     g_al);
    cudaGetSymbolAddress((void**)&w1h,    g_w1h);
    cudaGetSymbolAddress((void**)&w1l,    g_w1l);
    cudaGetSymbolAddress((void**)&w2h,    g_w2h);
    cudaGetSymbolAddress((void**)&w2l,    g_w2l);

    cudaFuncSetAttribute(gemm_mma, cudaFuncAttributeMaxDynamicSharedMemorySize, SM_TOT);

    const int nd_total = n_nodes * DIM;
    const dim3 gemm_grid(DIM / 128, (n_nodes + 127) / 128);
    const dim3 tr_grid(DIM / 32, DIM / 32), tr_blk(32, 8);

    // CSR build (shared by both layers)
    zero_cnt<<<(n_nodes + 255) / 256, 256>>>(cnt, n_nodes);
    hist_k<<<(tot + 255) / 256, 256>>>(ei, n_edges, n_nodes, cnt);
    scan_rowptr<<<1, 1024>>>(cnt, rowptr, cursor, n_nodes);
    fill_csr<<<(tot + 255) / 256, 256>>>(ei, n_edges, n_nodes, cursor, srcs);

    // weight splits (transposed)
    split_wT<<<tr_grid, tr_blk>>>(W1, w1h, w1l);
    split_wT<<<tr_grid, tr_blk>>>(W2, w2h, w2l);

    // ---------------- layer 1 ----------------
    split_x<<<(nd_total + 255) / 256, 256>>>(x, ah, al, nd_total);
    zero_ad<<<(n_nodes + 255) / 256, 256>>>(as_, ad_, n_nodes);
    gemm_mma<<<gemm_grid, 256, SM_TOT>>>(n_nodes, ah, al, w1h, w1l,
                                         as1, ad1, as_, ad_, h);
    gat_gather<<<(n_nodes + 7) / 8, 256>>>(rowptr, srcs, as_, ad_, h, b1,
                                           nullptr, ah, al, n_nodes, 1);

    // ---------------- layer 2 ----------------
    zero_ad<<<(n_nodes + 255) / 256, 256>>>(as_, ad_, n_nodes);
    gemm_mma<<<gemm_grid, 256, SM_TOT>>>(n_nodes, ah, al, w2h, w2l,
                                         as2, ad2, as_, ad_, h);
    gat_gather<<<(n_nodes + 7) / 8, 256>>>(rowptr, srcs, as_, ad_, h, b2,
                                           (float*)d_out, nullptr, nullptr, n_nodes, 0);
}

// round 8
// speedup vs baseline: 2.9589x; 1.0095x over previous
#include <cuda_runtime.h>
#include <cuda_bf16.h>
#include <math.h>
#include <stdint.h>

#define DIM   768
#define MAXN  10000
#define MAXE  100000

// ---------------- scratch (static device globals; no allocation) ----------------
__device__ float g_h [MAXN * DIM];     // h = x @ W (per-layer, reused)
__device__ float g_as1[MAXN], g_ad1[MAXN];
__device__ float g_as2[MAXN], g_ad2[MAXN];
__device__ int   g_cnt[MAXN];
__device__ int   g_rowptr[MAXN + 1];
__device__ int   g_cursor[MAXN];
__device__ int   g_srcs[MAXE + MAXN];
// bf16 split operands
__device__ __nv_bfloat16 g_ah[MAXN * DIM];
__device__ __nv_bfloat16 g_al[MAXN * DIM];
__device__ __nv_bfloat16 g_w1h[DIM * DIM], g_w1l[DIM * DIM];   // W1^T split
__device__ __nv_bfloat16 g_w2h[DIM * DIM], g_w2l[DIM * DIM];   // W2^T split

// ---------------- mma.sync helpers (sm_80+ path; valid on plain sm_103) ------
__device__ __forceinline__ void mma_bf16(float* c, const uint32_t* a, const uint32_t* b) {
    asm volatile(
        "mma.sync.aligned.m16n8k16.row.col.f32.bf16.bf16.f32 "
        "{%0,%1,%2,%3}, {%4,%5,%6,%7}, {%8,%9}, {%0,%1,%2,%3};"
        : "+f"(c[0]), "+f"(c[1]), "+f"(c[2]), "+f"(c[3])
        : "r"(a[0]), "r"(a[1]), "r"(a[2]), "r"(a[3]), "r"(b[0]), "r"(b[1]));
}
__device__ __forceinline__ void ldm4(uint32_t* r, uint32_t addr) {
    asm volatile("ldmatrix.sync.aligned.m8n8.x4.shared.b16 {%0,%1,%2,%3}, [%4];"
                 : "=r"(r[0]), "=r"(r[1]), "=r"(r[2]), "=r"(r[3]) : "r"(addr));
}
__device__ __forceinline__ void cpa16(uint32_t dst, const void* src, int src_bytes) {
    asm volatile("cp.async.ca.shared.global [%0], [%1], 16, %2;"
                 :: "r"(dst), "l"(src), "r"(src_bytes));
}
__device__ __forceinline__ void cpa_commit() {
    asm volatile("cp.async.commit_group;" ::: "memory");
}
template <int N>
__device__ __forceinline__ void cpa_wait() {
    asm volatile("cp.async.wait_group %0;" :: "n"(N) : "memory");
}

// ---------------- tensor-core GEMM + fused attention dots ----------------
// C = Ah*Bh + Ah*Bl + Al*Bh (fp32 accum). BM=BN=128, BK=32, 8 warps (2x4).
// Double-buffered cp.async staging. Epilogue also accumulates
// as_[m] += C[m,:] . att_s  and  ad_[m] += C[m,:] . att_d  via atomics.
#define LDSS     40                    // smem row stride in bf16 (80 B)
#define SM_ARR   (128 * LDSS * 2)      // 10240 B per array
#define SM_STAGE (SM_ARR * 4)          // 40960 B per stage
#define SM_TOT   (SM_STAGE * 2)        // 81920 B

__global__ __launch_bounds__(256, 2) void gemm_mma(
        int M,
        const __nv_bfloat16* __restrict__ Ah, const __nv_bfloat16* __restrict__ Al,
        const __nv_bfloat16* __restrict__ Bh, const __nv_bfloat16* __restrict__ Bl,
        const float* __restrict__ att_s, const float* __restrict__ att_d,
        float* __restrict__ as_, float* __restrict__ ad_,
        float* __restrict__ C) {
    extern __shared__ char dsm[];
    const uint32_t sb = (uint32_t)__cvta_generic_to_shared(dsm);

    const int tid  = threadIdx.x;
    const int lane = tid & 31;
    const int warp = tid >> 5;
    const int wm   = warp >> 2;          // 0..1  (64 rows each)
    const int wn   = warp & 3;           // 0..3  (32 cols each)
    const int m0   = blockIdx.y * 128;
    const int n0   = blockIdx.x * 128;
    const int rowsv = min(128, M - m0);

    const int srow = tid >> 1;
    const int schk0 = (tid & 1) * 2;

    float acc[4][4][4];
#pragma unroll
    for (int i = 0; i < 4; i++)
#pragma unroll
        for (int j = 0; j < 4; j++)
#pragma unroll
            for (int q = 0; q < 4; q++) acc[i][j][q] = 0.f;

    const int amat = lane >> 3, ar = lane & 7;
    const int a_row_off = ((amat & 1) << 3) + ar;
    const int a_col_off = (amat >> 1) << 3;
    const int b_row_off = ((amat >> 1) << 3) + ar;
    const int b_col_off = (amat & 1) << 3;

    const int NT = DIM / 32;

    auto stage = [&](int s, int k0) {
        const uint32_t base = sb + s * SM_STAGE;
        const bool av = srow < rowsv;
        const int arow = av ? (m0 + srow) : m0;
        const int asz  = av ? 16 : 0;
#pragma unroll
        for (int c = 0; c < 2; c++) {
            const int chk = schk0 + c;
            const uint32_t so = (uint32_t)(srow * 80 + chk * 16);
            const size_t ga = (size_t)arow * DIM + k0 + chk * 8;
            const size_t gb = (size_t)(n0 + srow) * DIM + k0 + chk * 8;
            cpa16(base + 0 * SM_ARR + so, Ah + ga, asz);
            cpa16(base + 1 * SM_ARR + so, Al + ga, asz);
            cpa16(base + 2 * SM_ARR + so, Bh + gb, 16);
            cpa16(base + 3 * SM_ARR + so, Bl + gb, 16);
        }
    };

    stage(0, 0);
    cpa_commit();

    for (int it = 0; it < NT; it++) {
        const int buf = it & 1;
        if (it + 1 < NT) { stage(buf ^ 1, (it + 1) * 32); cpa_commit(); cpa_wait<1>(); }
        else             { cpa_wait<0>(); }
        __syncthreads();

        const uint32_t bA = sb + buf * SM_STAGE;
#pragma unroll
        for (int kc = 0; kc < 2; kc++) {
            uint32_t ah[4][4], al[4][4];
#pragma unroll
            for (int mt = 0; mt < 4; mt++) {
                const uint32_t off =
                    (uint32_t)((wm * 64 + mt * 16 + a_row_off) * 80 +
                               (kc * 16 + a_col_off) * 2);
                ldm4(ah[mt], bA + 0 * SM_ARR + off);
                ldm4(al[mt], bA + 1 * SM_ARR + off);
            }
            uint32_t bh[2][4], bl[2][4];
#pragma unroll
            for (int p = 0; p < 2; p++) {
                const uint32_t off =
                    (uint32_t)((wn * 32 + p * 16 + b_row_off) * 80 +
                               (kc * 16 + b_col_off) * 2);
                ldm4(bh[p], bA + 2 * SM_ARR + off);
                ldm4(bl[p], bA + 3 * SM_ARR + off);
            }
#pragma unroll
            for (int mt = 0; mt < 4; mt++)
#pragma unroll
                for (int nt = 0; nt < 4; nt++) {
                    const uint32_t* bhf = &bh[nt >> 1][(nt & 1) * 2];
                    const uint32_t* blf = &bl[nt >> 1][(nt & 1) * 2];
                    mma_bf16(acc[mt][nt], ah[mt], bhf);
                    mma_bf16(acc[mt][nt], ah[mt], blf);
                    mma_bf16(acc[mt][nt], al[mt], bhf);
                }
        }
        __syncthreads();
    }

    // ---- epilogue: store C + fused attention dot partials ----
    const int gr = lane >> 2, gc = (lane & 3) * 2;
#pragma unroll
    for (int mt = 0; mt < 4; mt++) {
        float s0 = 0.f, s1 = 0.f, d0 = 0.f, d1 = 0.f;
#pragma unroll
        for (int nt = 0; nt < 4; nt++) {
            const int m = m0 + wm * 64 + mt * 16 + gr;
            const int n = n0 + wn * 32 + nt * 8 + gc;
            const float2 av = *reinterpret_cast<const float2*>(att_s + n);
            const float2 dv = *reinterpret_cast<const float2*>(att_d + n);
            s0 += acc[mt][nt][0] * av.x + acc[mt][nt][1] * av.y;
            s1 += acc[mt][nt][2] * av.x + acc[mt][nt][3] * av.y;
            d0 += acc[mt][nt][0] * dv.x + acc[mt][nt][1] * dv.y;
            d1 += acc[mt][nt][2] * dv.x + acc[mt][nt][3] * dv.y;
            if (m < M)
                *reinterpret_cast<float2*>(&C[(size_t)m * DIM + n]) =
                    make_float2(acc[mt][nt][0], acc[mt][nt][1]);
            if (m + 8 < M)
                *reinterpret_cast<float2*>(&C[(size_t)(m + 8) * DIM + n]) =
                    make_float2(acc[mt][nt][2], acc[mt][nt][3]);
        }
#pragma unroll
        for (int o = 1; o < 4; o <<= 1) {
            s0 += __shfl_xor_sync(0xffffffffu, s0, o);
            s1 += __shfl_xor_sync(0xffffffffu, s1, o);
            d0 += __shfl_xor_sync(0xffffffffu, d0, o);
            d1 += __shfl_xor_sync(0xffffffffu, d1, o);
        }
        if ((lane & 3) == 0) {
            const int m = m0 + wm * 64 + mt * 16 + gr;
            if (m < M)     { atomicAdd(&as_[m], s0);     atomicAdd(&ad_[m], d0); }
            if (m + 8 < M) { atomicAdd(&as_[m + 8], s1); atomicAdd(&ad_[m + 8], d1); }
        }
    }
}

// ---------------- bf16 split conversions ----------------
__global__ void split_x(const float* __restrict__ x, __nv_bfloat16* __restrict__ hi,
                        __nv_bfloat16* __restrict__ lo, int total) {
    const int i = blockIdx.x * blockDim.x + threadIdx.x;
    if (i >= total) return;
    const float v = x[i];
    const __nv_bfloat16 h = __float2bfloat16(v);
    hi[i] = h;
    lo[i] = __float2bfloat16(v - __bfloat162float(h));
}

// batched: z=0 -> W1, z=1 -> W2.  W [K][N] row-major -> Wt hi/lo [N][K]
__global__ void split_wT(const float* __restrict__ Wa, const float* __restrict__ Wb,
                         __nv_bfloat16* __restrict__ hA, __nv_bfloat16* __restrict__ lA,
                         __nv_bfloat16* __restrict__ hB, __nv_bfloat16* __restrict__ lB) {
    const float* W = blockIdx.z ? Wb : Wa;
    __nv_bfloat16* hiT = blockIdx.z ? hB : hA;
    __nv_bfloat16* loT = blockIdx.z ? lB : lA;
    __shared__ float t[32][33];
    const int bx = blockIdx.x * 32, by = blockIdx.y * 32;
    const int tx = threadIdx.x, ty = threadIdx.y;
    #pragma unroll
    for (int j = 0; j < 4; j++)
        t[ty + j * 8][tx] = W[(size_t)(by + ty + j * 8) * DIM + bx + tx];
    __syncthreads();
    #pragma unroll
    for (int j = 0; j < 4; j++) {
        const float v = t[tx][ty + j * 8];
        const __nv_bfloat16 h = __float2bfloat16(v);
        const size_t o = (size_t)(bx + ty + j * 8) * DIM + by + tx;
        hiT[o] = h;
        loT[o] = __float2bfloat16(v - __bfloat162float(h));
    }
}

// zero cnt + both layers' attention accumulators in one launch
__global__ void zero_all(int* __restrict__ cnt,
                         float* __restrict__ a1, float* __restrict__ d1,
                         float* __restrict__ a2, float* __restrict__ d2, int n) {
    const int i = blockIdx.x * blockDim.x + threadIdx.x;
    if (i < n) { cnt[i] = 0; a1[i] = 0.f; d1[i] = 0.f; a2[i] = 0.f; d2[i] = 0.f; }
}

// ---------------- CSR build ----------------
__global__ void hist_k(const int* __restrict__ ei, int nE, int nN, int* __restrict__ cnt) {
    const int e = blockIdx.x * blockDim.x + threadIdx.x;
    if (e >= nE + nN) return;
    const int d = (e < nE) ? ei[nE + e] : (e - nE);
    atomicAdd(&cnt[d], 1);
}
__global__ void scan_rowptr(const int* __restrict__ cnt, int* __restrict__ rowptr,
                            int* __restrict__ cursor, int n) {
    __shared__ int sh[32];
    __shared__ int carry_sh;
    const int tid = threadIdx.x, lane = tid & 31, wid = tid >> 5;
    if (tid == 0) carry_sh = 0;
    __syncthreads();
    for (int base = 0; base < n; base += 1024) {
        const int i = base + tid;
        const int v = (i < n) ? cnt[i] : 0;
        int x = v;
#pragma unroll
        for (int o = 1; o < 32; o <<= 1) {
            int y = __shfl_up_sync(0xffffffffu, x, o);
            if (lane >= o) x += y;
        }
        if (lane == 31) sh[wid] = x;
        __syncthreads();
        if (wid == 0) {
            int s = sh[lane];
#pragma unroll
            for (int o = 1; o < 32; o <<= 1) {
                int y = __shfl_up_sync(0xffffffffu, s, o);
                if (lane >= o) s += y;
            }
            sh[lane] = s;
        }
        __syncthreads();
        const int incl = x + (wid > 0 ? sh[wid - 1] : 0);
        const int carry = carry_sh;
        if (i < n) { rowptr[i] = carry + incl - v; cursor[i] = carry + incl - v; }
        __syncthreads();
        if (tid == 1023) carry_sh = carry + incl;
        __syncthreads();
    }
    if (threadIdx.x == 0) rowptr[n] = carry_sh;
}
__global__ void fill_csr(const int* __restrict__ ei, int nE, int nN,
                         int* __restrict__ cursor, int* __restrict__ srcs) {
    const int e = blockIdx.x * blockDim.x + threadIdx.x;
    if (e >= nE + nN) return;
    int s, d;
    if (e < nE) { s = ei[e]; d = ei[nE + e]; }
    else        { s = d = e - nE; }
    const int pos = atomicAdd(&cursor[d], 1);
    srcs[pos] = s;
}

// ---------------- fused per-node softmax + gather ----------------
// mode 0: write float out (layer 2, no relu)
// mode 1: relu, then write bf16 hi/lo split (layer 1 -> layer 2 GEMM operands)
__global__ void gat_gather(const int* __restrict__ rowptr, const int* __restrict__ srcs,
                           const float* __restrict__ as_, const float* __restrict__ ad_,
                           const float* __restrict__ h, const float* __restrict__ bias,
                           float* __restrict__ outF,
                           __nv_bfloat16* __restrict__ outH,
                           __nv_bfloat16* __restrict__ outL,
                           int n, int mode) {
    const int node = blockIdx.x * (blockDim.x >> 5) + (threadIdx.x >> 5);
    const int lane = threadIdx.x & 31;
    if (node >= n) return;
    const int beg = rowptr[node], end = rowptr[node + 1];
    const float adn = ad_[node];

    float mx = -INFINITY;
    for (int j = beg + lane; j < end; j += 32) {
        float v = as_[srcs[j]] + adn;
        v = v > 0.f ? v : 0.2f * v;
        mx = fmaxf(mx, v);
    }
#pragma unroll
    for (int o = 16; o; o >>= 1) mx = fmaxf(mx, __shfl_xor_sync(0xffffffffu, mx, o));

    float den = 0.f;
    for (int j = beg + lane; j < end; j += 32) {
        float v = as_[srcs[j]] + adn;
        v = v > 0.f ? v : 0.2f * v;
        den += expf(v - mx);
    }
#pragma unroll
    for (int o = 16; o; o >>= 1) den += __shfl_xor_sync(0xffffffffu, den, o);
    const float inv = 1.f / den;

    float4 acc[DIM / 128];
#pragma unroll
    for (int q = 0; q < DIM / 128; q++) acc[q] = make_float4(0.f, 0.f, 0.f, 0.f);

    for (int j0 = beg; j0 < end; j0 += 32) {
        const int j = j0 + lane;
        float w = 0.f; int s = 0;
        if (j < end) {
            s = srcs[j];
            float v = as_[s] + adn;
            v = v > 0.f ? v : 0.2f * v;
            w = expf(v - mx) * inv;
        }
        const int cnt = min(32, end - j0);
        for (int t = 0; t < cnt; t++) {
            const float wt = __shfl_sync(0xffffffffu, w, t);
            const int   st = __shfl_sync(0xffffffffu, s, t);
            const float4* hr = reinterpret_cast<const float4*>(h + (size_t)st * DIM);
#pragma unroll
            for (int q = 0; q < DIM / 128; q++) {
                const float4 v = hr[lane + 32 * q];
                acc[q].x += wt * v.x; acc[q].y += wt * v.y;
                acc[q].z += wt * v.z; acc[q].w += wt * v.w;
            }
        }
    }

    const float4* b4 = reinterpret_cast<const float4*>(bias);
#pragma unroll
    for (int q = 0; q < DIM / 128; q++) {
        const float4 bv = b4[lane + 32 * q];
        float4 r = make_float4(acc[q].x + bv.x, acc[q].y + bv.y,
                               acc[q].z + bv.z, acc[q].w + bv.w);
        if (mode == 1) {
            r.x = fmaxf(r.x, 0.f); r.y = fmaxf(r.y, 0.f);
            r.z = fmaxf(r.z, 0.f); r.w = fmaxf(r.w, 0.f);
            const size_t off = (size_t)node * DIM + (lane + 32 * q) * 4;
            float hx = __bfloat162float(__float2bfloat16(r.x));
            float hy = __bfloat162float(__float2bfloat16(r.y));
            float hz = __bfloat162float(__float2bfloat16(r.z));
            float hw = __bfloat162float(__float2bfloat16(r.w));
            __nv_bfloat162 h01, h23, l01, l23;
            h01 = __nv_bfloat162(__float2bfloat16(r.x), __float2bfloat16(r.y));
            h23 = __nv_bfloat162(__float2bfloat16(r.z), __float2bfloat16(r.w));
            l01 = __nv_bfloat162(__float2bfloat16(r.x - hx), __float2bfloat16(r.y - hy));
            l23 = __nv_bfloat162(__float2bfloat16(r.z - hz), __float2bfloat16(r.w - hw));
            uint2 hp = make_uint2(*(uint32_t*)&h01, *(uint32_t*)&h23);
            uint2 lp = make_uint2(*(uint32_t*)&l01, *(uint32_t*)&l23);
            *reinterpret_cast<uint2*>(outH + off) = hp;
            *reinterpret_cast<uint2*>(outL + off) = lp;
        } else {
            float4* o4 = reinterpret_cast<float4*>(outF + (size_t)node * DIM);
            o4[lane + 32 * q] = r;
        }
    }
}

// ---------------- launch ----------------
extern "C" void kernel_launch(void* const* d_in, const int* in_sizes, int n_in,
                              void* d_out, int out_size) {
    const float* x    = (const float*)d_in[0];
    const int*   ei   = (const int*)d_in[1];     // int32 edge_index [2, E]
    const float* W1   = (const float*)d_in[2];
    const float* as1  = (const float*)d_in[3];
    const float* ad1  = (const float*)d_in[4];
    const float* b1   = (const float*)d_in[5];
    const float* W2   = (const float*)d_in[6];
    const float* as2  = (const float*)d_in[7];
    const float* ad2  = (const float*)d_in[8];
    const float* b2   = (const float*)d_in[9];

    const int n_nodes = in_sizes[0] / DIM;
    const int n_edges = in_sizes[1] / 2;
    const int tot     = n_edges + n_nodes;

    float *h, *asL1, *adL1, *asL2, *adL2;
    int *cnt, *rowptr, *cursor, *srcs;
    __nv_bfloat16 *ah, *al, *w1h, *w1l, *w2h, *w2l;
    cudaGetSymbolAddress((void**)&h,      g_h);
    cudaGetSymbolAddress((void**)&asL1,   g_as1);
    cudaGetSymbolAddress((void**)&adL1,   g_ad1);
    cudaGetSymbolAddress((void**)&asL2,   g_as2);
    cudaGetSymbolAddress((void**)&adL2,   g_ad2);
    cudaGetSymbolAddress((void**)&cnt,    g_cnt);
    cudaGetSymbolAddress((void**)&rowptr, g_rowptr);
    cudaGetSymbolAddress((void**)&cursor, g_cursor);
    cudaGetSymbolAddress((void**)&srcs,   g_srcs);
    cudaGetSymbolAddress((void**)&ah,     g_ah);
    cudaGetSymbolAddress((void**)&al,     g_al);
    cudaGetSymbolAddress((void**)&w1h,    g_w1h);
    cudaGetSymbolAddress((void**)&w1l,    g_w1l);
    cudaGetSymbolAddress((void**)&w2h,    g_w2h);
    cudaGetSymbolAddress((void**)&w2l,    g_w2l);

    cudaFuncSetAttribute(gemm_mma, cudaFuncAttributeMaxDynamicSharedMemorySize, SM_TOT);

    const int nd_total = n_nodes * DIM;
    const dim3 gemm_grid(DIM / 128, (n_nodes + 127) / 128);
    const dim3 tr_grid(DIM / 32, DIM / 32, 2), tr_blk(32, 8);

    // 0: zero everything (cnt + both layers' attention accumulators)
    zero_all<<<(n_nodes + 255) / 256, 256>>>(cnt, asL1, adL1, asL2, adL2, n_nodes);
    // 1: both weight splits (batched)
    split_wT<<<tr_grid, tr_blk>>>(W1, W2, w1h, w1l, w2h, w2l);
    // 2: layer-1 input split
    split_x<<<(nd_total + 255) / 256, 256>>>(x, ah, al, nd_total);
    // 3: layer-1 GEMM  <-- ncu capture slot
    gemm_mma<<<gemm_grid, 256, SM_TOT>>>(n_nodes, ah, al, w1h, w1l,
                                         as1, ad1, asL1, adL1, h);
    // 4-6: CSR build (only needed by gather)
    hist_k<<<(tot + 255) / 256, 256>>>(ei, n_edges, n_nodes, cnt);
    scan_rowptr<<<1, 1024>>>(cnt, rowptr, cursor, n_nodes);
    fill_csr<<<(tot + 255) / 256, 256>>>(ei, n_edges, n_nodes, cursor, srcs);
    // 7: layer-1 gather (writes bf16 split for layer 2)
    gat_gather<<<(n_nodes + 7) / 8, 256>>>(rowptr, srcs, asL1, adL1, h, b1,
                                           nullptr, ah, al, n_nodes, 1);
    // 8: layer-2 GEMM
    gemm_mma<<<gemm_grid, 256, SM_TOT>>>(n_nodes, ah, al, w2h, w2l,
                                         as2, ad2, asL2, adL2, h);
    // 9: layer-2 gather -> output
    gat_gather<<<(n_nodes + 7) / 8, 256>>>(rowptr, srcs, asL2, adL2, h, b2,
                                           (float*)d_out, nullptr, nullptr, n_nodes, 0);
}